// round 14
// baseline (speedup 1.0000x reference)
#include <cuda_runtime.h>
#include <cuda_bf16.h>
#include <cstdint>

#define NTOK   8192     // 8 * 1024 tokens
#define DMODEL 1024
#define NQKV   512      // H * D_K
#define NCAT   1536     // Q|K|V concatenated
#define SEQ    1024
#define NHEAD  8
#define DHEAD  64

// -------------------- scratch (device globals: allocation-guard safe) ----------
__device__ __nv_bfloat16 g_xh[NTOK * DMODEL], g_xl[NTOK * DMODEL];
__device__ __nv_bfloat16 g_qkvh[NTOK * NCAT], g_qkvl[NTOK * NCAT];
__device__ __nv_bfloat16 g_aoh[NTOK * NQKV],  g_aol[NTOK * NQKV];
__device__ __nv_bfloat16 g_wch[NCAT * DMODEL], g_wcl[NCAT * DMODEL];
__device__ __nv_bfloat16 g_woh[DMODEL * NQKV], g_wol[DMODEL * NQKV];
__device__ float g_bcat[NCAT];

extern __shared__ unsigned char dynsmem[];

// -------------------- PTX helpers (base-target sm_80+ instructions) ------------
__device__ __forceinline__ uint32_t smem_to_u32(const void* p) {
    uint32_t a;
    asm("{ .reg .u64 t; cvta.to.shared.u64 t, %1; cvt.u32.u64 %0, t; }"
        : "=r"(a) : "l"(p));
    return a;
}
__device__ __forceinline__ void cp16(uint32_t dst, const void* src) {
    asm volatile("cp.async.ca.shared.global [%0], [%1], 16;"
                 :: "r"(dst), "l"(src) : "memory");
}
#define CP_COMMIT() asm volatile("cp.async.commit_group;" ::: "memory")
#define CP_WAIT1()  asm volatile("cp.async.wait_group 1;" ::: "memory")
#define CP_WAIT0()  asm volatile("cp.async.wait_group 0;" ::: "memory")

__device__ __forceinline__ void ldsm_x4(uint32_t* r, uint32_t addr) {
    asm volatile("ldmatrix.sync.aligned.m8n8.x4.shared.b16 {%0,%1,%2,%3}, [%4];"
                 : "=r"(r[0]), "=r"(r[1]), "=r"(r[2]), "=r"(r[3]) : "r"(addr));
}
__device__ __forceinline__ void ldsm_x2(uint32_t* r, uint32_t addr) {
    asm volatile("ldmatrix.sync.aligned.m8n8.x2.shared.b16 {%0,%1}, [%2];"
                 : "=r"(r[0]), "=r"(r[1]) : "r"(addr));
}
__device__ __forceinline__ void ldsm_x2t(uint32_t* r, uint32_t addr) {
    asm volatile("ldmatrix.sync.aligned.m8n8.x2.trans.shared.b16 {%0,%1}, [%2];"
                 : "=r"(r[0]), "=r"(r[1]) : "r"(addr));
}
__device__ __forceinline__ void mma16816(float* c, const uint32_t* a, const uint32_t* b) {
    asm volatile("mma.sync.aligned.m16n8k16.row.col.f32.bf16.bf16.f32 "
                 "{%0,%1,%2,%3}, {%4,%5,%6,%7}, {%8,%9}, {%0,%1,%2,%3};"
                 : "+f"(c[0]), "+f"(c[1]), "+f"(c[2]), "+f"(c[3])
                 : "r"(a[0]), "r"(a[1]), "r"(a[2]), "r"(a[3]),
                   "r"(b[0]), "r"(b[1]));
}
__device__ __forceinline__ uint32_t pkbf2(float lo, float hi) {
    __nv_bfloat162 t = __floats2bfloat162_rn(lo, hi);
    return reinterpret_cast<uint32_t&>(t);
}

// -------------------- pre-pass: split fp32 -> bf16 hi/lo -----------------------
__global__ void split_kernel(const float* __restrict__ src,
                             __nv_bfloat16* __restrict__ hi,
                             __nv_bfloat16* __restrict__ lo, int n2) {
    int i = blockIdx.x * blockDim.x + threadIdx.x;
    if (i < n2) {
        float2 v = ((const float2*)src)[i];
        __nv_bfloat16 h0 = __float2bfloat16(v.x);
        __nv_bfloat16 h1 = __float2bfloat16(v.y);
        __nv_bfloat16 l0 = __float2bfloat16(v.x - __bfloat162float(h0));
        __nv_bfloat16 l1 = __float2bfloat16(v.y - __bfloat162float(h1));
        ((__nv_bfloat162*)hi)[i] = __halves2bfloat162(h0, h1);
        ((__nv_bfloat162*)lo)[i] = __halves2bfloat162(l0, l1);
    }
}

// -------------------- pre-pass: bias concat ------------------------------------
__global__ void bias_cat(const float* __restrict__ bq, const float* __restrict__ bk,
                         const float* __restrict__ bv, float* __restrict__ bc) {
    int i = blockIdx.x * blockDim.x + threadIdx.x;
    if (i < NCAT)
        bc[i] = (i < 512) ? bq[i] : (i < 1024) ? bk[i - 512] : bv[i - 1024];
}

// -------------------- pre-pass: W[K,N] fp32 -> Wt[N,K] bf16 hi/lo --------------
__global__ void transpose_split3(const float* __restrict__ W0, __nv_bfloat16* __restrict__ T0h,
                                 __nv_bfloat16* __restrict__ T0l,
                                 const float* __restrict__ W1, __nv_bfloat16* __restrict__ T1h,
                                 __nv_bfloat16* __restrict__ T1l,
                                 const float* __restrict__ W2, __nv_bfloat16* __restrict__ T2h,
                                 __nv_bfloat16* __restrict__ T2l,
                                 int Kd, int Nd) {
    __shared__ float t[32][33];
    const float* W = (blockIdx.z == 0) ? W0 : (blockIdx.z == 1) ? W1 : W2;
    __nv_bfloat16* Th = (blockIdx.z == 0) ? T0h : (blockIdx.z == 1) ? T1h : T2h;
    __nv_bfloat16* Tl = (blockIdx.z == 0) ? T0l : (blockIdx.z == 1) ? T1l : T2l;
    int k0 = blockIdx.y * 32, n0 = blockIdx.x * 32;
    for (int i = threadIdx.y; i < 32; i += 8)
        t[i][threadIdx.x] = W[(size_t)(k0 + i) * Nd + n0 + threadIdx.x];
    __syncthreads();
    for (int i = threadIdx.y; i < 32; i += 8) {
        float v = t[threadIdx.x][i];
        __nv_bfloat16 h = __float2bfloat16(v);
        __nv_bfloat16 l = __float2bfloat16(v - __bfloat162float(h));
        size_t o = (size_t)(n0 + i) * Kd + k0 + threadIdx.x;
        Th[o] = h; Tl[o] = l;
    }
}

// -------------------- mixed-precision HMMA GEMM: C = A @ B^T + bias ------------
// CTA tile 128x128, BK=32, 512 threads = 16 warps of 32x32, double-buffered.
// 4 warps/SMSP + small per-thread state (acc=32 regs) -> latency hidden, no
// spills (R9 had 4 warps/SMSP but spilled at acc=64; R8 had no spills but only
// 2 warps/SMSP — this takes the missing quadrant).
// OM=0: fp32 out, bf16x3. OM=3: fused QKV — n0<1024 1-product, V cols 3-product.
#define GASTRIDE   40                       // bf16 elems per smem row
#define GMAT_BYTES (128 * GASTRIDE * 2)     // 10240 B per matrix tile
#define GSTAGE     (4 * GMAT_BYTES)         // Ah, Al, Bh, Bl = 40960 B
#define GSM_TOTAL  (2 * GSTAGE)             // double buffer = 81920 B

template <int OM>
__global__ __launch_bounds__(512)
void gemm_bf16x3(const __nv_bfloat16* __restrict__ Ah, const __nv_bfloat16* __restrict__ Al,
                 const __nv_bfloat16* __restrict__ Bh, const __nv_bfloat16* __restrict__ Bl,
                 const float* __restrict__ bias, float* __restrict__ Cf,
                 __nv_bfloat16* __restrict__ Ch, __nv_bfloat16* __restrict__ Cl,
                 int K, int N) {
    const uint32_t smem_base = smem_to_u32(dynsmem);
    const int tid  = threadIdx.x;
    const int wid  = tid >> 5, lane = tid & 31;
    const int m0 = blockIdx.y * 128, n0 = blockIdx.x * 128;
    const bool fullp = (OM != 3) || (n0 >= 1024);   // 3-product vs 1-product tile

    // ---- loader: one thread = one row of one matrix, 4x cp16 (64 B payload) ---
    const int mat = tid >> 7;           // 0=Ah 1=Al 2=Bh 3=Bl
    const int rr  = tid & 127;
    const __nv_bfloat16* mats[4] = { Ah, Al, Bh, Bl };
    const int brow = (mat < 2) ? m0 : n0;
    const __nv_bfloat16* gsrc = mats[mat] + (size_t)(brow + rr) * K;
    const uint32_t sdst = smem_base + mat * GMAT_BYTES + rr * (GASTRIDE * 2);
    const bool ldme = fullp || mat == 0 || mat == 2;   // skip Al/Bl on 1-product tiles

    // ---- compute mapping: 16 warps = 4 (m) x 4 (n), 32x32 each ----------------
    const int wm = (wid & 3) * 32;
    const int wn = (wid >> 2) * 32;
    const int aRowOff = lane & 15;
    const int aColOff = (lane & 16) ? 8 : 0;
    const int bRowOff = lane & 7;
    const int bColOff = (lane & 8) ? 8 : 0;

    float acc[2][4][4];
#pragma unroll
    for (int i = 0; i < 2; i++)
#pragma unroll
        for (int j = 0; j < 4; j++)
#pragma unroll
            for (int c = 0; c < 4; c++) acc[i][j][c] = 0.0f;

    const int nstage = K >> 5;
    if (ldme) {
#pragma unroll
        for (int c = 0; c < 4; ++c) cp16(sdst + c * 16, gsrc + c * 8);
    }
    CP_COMMIT();

    for (int s = 0; s < nstage; ++s) {
        if (s + 1 < nstage) {
            const int k0 = (s + 1) << 5;
            const uint32_t boff = ((s + 1) & 1) * GSTAGE;
            if (ldme) {
#pragma unroll
                for (int c = 0; c < 4; ++c) cp16(sdst + boff + c * 16, gsrc + k0 + c * 8);
            }
            CP_COMMIT();
            CP_WAIT1();
        } else {
            CP_WAIT0();
        }
        __syncthreads();

        const uint32_t sb = smem_base + (s & 1) * GSTAGE;
        const uint32_t sbB = sb + 2 * GMAT_BYTES;
        if (fullp) {
#pragma unroll
            for (int kc = 0; kc < 32; kc += 16) {
                uint32_t ah[2][4], al[2][4], bh[4][2], bl[4][2];
#pragma unroll
                for (int i = 0; i < 2; ++i) {
                    uint32_t addr = sb + (wm + 16 * i + aRowOff) * (GASTRIDE * 2)
                                       + (kc + aColOff) * 2;
                    ldsm_x4(ah[i], addr);
                    ldsm_x4(al[i], addr + GMAT_BYTES);
                }
#pragma unroll
                for (int j = 0; j < 4; ++j) {
                    uint32_t addr = sbB + (wn + 8 * j + bRowOff) * (GASTRIDE * 2)
                                        + (kc + bColOff) * 2;
                    ldsm_x2(bh[j], addr);
                    ldsm_x2(bl[j], addr + GMAT_BYTES);
                }
#pragma unroll
                for (int i = 0; i < 2; ++i)
#pragma unroll
                    for (int j = 0; j < 4; ++j) {
                        mma16816(acc[i][j], ah[i], bh[j]);
                        mma16816(acc[i][j], ah[i], bl[j]);
                        mma16816(acc[i][j], al[i], bh[j]);
                    }
            }
        } else {
#pragma unroll
            for (int kc = 0; kc < 32; kc += 16) {
                uint32_t ah[2][4], bh[4][2];
#pragma unroll
                for (int i = 0; i < 2; ++i)
                    ldsm_x4(ah[i], sb + (wm + 16 * i + aRowOff) * (GASTRIDE * 2)
                                      + (kc + aColOff) * 2);
#pragma unroll
                for (int j = 0; j < 4; ++j)
                    ldsm_x2(bh[j], sbB + (wn + 8 * j + bRowOff) * (GASTRIDE * 2)
                                       + (kc + bColOff) * 2);
#pragma unroll
                for (int i = 0; i < 2; ++i)
#pragma unroll
                    for (int j = 0; j < 4; ++j)
                        mma16816(acc[i][j], ah[i], bh[j]);
            }
        }
        __syncthreads();
    }

    // ---- epilogue ----
    const int er = lane >> 2;
    const int ec = (lane & 3) * 2;
#pragma unroll
    for (int j = 0; j < 4; ++j) {
        const int n = n0 + wn + 8 * j + ec;
        const float b0 = bias[n], b1 = bias[n + 1];
#pragma unroll
        for (int i = 0; i < 2; ++i) {
            const int m = m0 + wm + 16 * i + er;
            float v0 = acc[i][j][0] + b0, v1 = acc[i][j][1] + b1;
            float v2 = acc[i][j][2] + b0, v3 = acc[i][j][3] + b1;
            if (OM == 0) {
                *(float2*)(Cf + (size_t)m * N + n)       = make_float2(v0, v1);
                *(float2*)(Cf + (size_t)(m + 8) * N + n) = make_float2(v2, v3);
            } else {
                __nv_bfloat16 h0 = __float2bfloat16(v0), h1 = __float2bfloat16(v1);
                __nv_bfloat16 h2 = __float2bfloat16(v2), h3 = __float2bfloat16(v3);
                *(__nv_bfloat162*)(Ch + (size_t)m * N + n) = __halves2bfloat162(h0, h1);
                *(__nv_bfloat162*)(Ch + (size_t)(m + 8) * N + n) = __halves2bfloat162(h2, h3);
                if (OM == 3 && n >= 1024) {
                    __nv_bfloat16 l0 = __float2bfloat16(v0 - __bfloat162float(h0));
                    __nv_bfloat16 l1 = __float2bfloat16(v1 - __bfloat162float(h1));
                    __nv_bfloat16 l2 = __float2bfloat16(v2 - __bfloat162float(h2));
                    __nv_bfloat16 l3 = __float2bfloat16(v3 - __bfloat162float(h3));
                    *(__nv_bfloat162*)(Cl + (size_t)m * N + n) = __halves2bfloat162(l0, l1);
                    *(__nv_bfloat162*)(Cl + (size_t)(m + 8) * N + n) = __halves2bfloat162(l2, l3);
                }
            }
        }
    }
}

// -------------------- HMMA flash attention (validated R7; stride = NCAT) -------
#define ASTR 72   // bf16 per smem row

__global__ __launch_bounds__(128)
void attn_mma(const __nv_bfloat16* __restrict__ QKVh, const __nv_bfloat16* __restrict__ QKVl,
              __nv_bfloat16* __restrict__ AOh, __nv_bfloat16* __restrict__ AOl) {
    __shared__ __align__(16) __nv_bfloat16 Qs[64 * ASTR];
    __shared__ __align__(16) __nv_bfloat16 Ks[64 * ASTR];
    __shared__ __align__(16) __nv_bfloat16 Vhs[64 * ASTR];
    __shared__ __align__(16) __nv_bfloat16 Vls[64 * ASTR];

    const int tid = threadIdx.x, wid = tid >> 5, lane = tid & 31;
    const int q0 = blockIdx.x * 64, h = blockIdx.y, b = blockIdx.z;
    const size_t rowbase = (size_t)b * SEQ;
    const int coff = h * DHEAD;

    const __nv_bfloat16* Qp  = QKVh + coff;            // Q cols [0,512)
    const __nv_bfloat16* Kp  = QKVh + 512 + coff;      // K cols [512,1024)
    const __nv_bfloat16* Vhp = QKVh + 1024 + coff;     // V cols [1024,1536)
    const __nv_bfloat16* Vlp = QKVl + 1024 + coff;

    const int lr = tid >> 1, lc = (tid & 1) * 32;
    {
        const __nv_bfloat16* src = Qp + (rowbase + q0 + lr) * NCAT + lc;
#pragma unroll
        for (int c = 0; c < 4; ++c)
            *(uint4*)&Qs[lr * ASTR + lc + 8 * c] = *(const uint4*)(src + 8 * c);
    }
    __syncthreads();

    const uint32_t qbase = smem_to_u32(Qs), kbase = smem_to_u32(Ks);
    const uint32_t vhb = smem_to_u32(Vhs), vlb = smem_to_u32(Vls);
    const int wq = wid * 16;

    uint32_t qf[4][4];
#pragma unroll
    for (int ks = 0; ks < 4; ++ks)
        ldsm_x4(qf[ks], qbase + ((wq + (lane & 15)) * ASTR + ks * 16
                                 + ((lane & 16) ? 8 : 0)) * 2);

    float oacc[8][4];
#pragma unroll
    for (int j = 0; j < 8; ++j)
#pragma unroll
        for (int c = 0; c < 4; ++c) oacc[j][c] = 0.0f;
    float mrow0 = -1e30f, mrow1 = -1e30f, lrow0 = 0.0f, lrow1 = 0.0f;

    for (int kv0 = 0; kv0 < SEQ; kv0 += 64) {
        __syncthreads();
        {
            const size_t grow = (rowbase + kv0 + lr) * NCAT + lc;
            const int so = lr * ASTR + lc;
#pragma unroll
            for (int c = 0; c < 4; ++c) {
                *(uint4*)&Ks[so + 8 * c]  = *(const uint4*)(Kp  + grow + 8 * c);
                *(uint4*)&Vhs[so + 8 * c] = *(const uint4*)(Vhp + grow + 8 * c);
                *(uint4*)&Vls[so + 8 * c] = *(const uint4*)(Vlp + grow + 8 * c);
            }
        }
        __syncthreads();

        float s[8][4];
#pragma unroll
        for (int j = 0; j < 8; ++j)
#pragma unroll
            for (int c = 0; c < 4; ++c) s[j][c] = 0.0f;
#pragma unroll
        for (int ks = 0; ks < 4; ++ks)
#pragma unroll
            for (int j = 0; j < 8; ++j) {
                uint32_t kf[2];
                ldsm_x2(kf, kbase + ((8 * j + (lane & 7)) * ASTR + ks * 16
                                     + ((lane & 8) ? 8 : 0)) * 2);
                mma16816(s[j], qf[ks], kf);
            }

        float tmax0 = -1e30f, tmax1 = -1e30f;
#pragma unroll
        for (int j = 0; j < 8; ++j) {
            s[j][0] *= 0.125f; s[j][1] *= 0.125f; s[j][2] *= 0.125f; s[j][3] *= 0.125f;
            tmax0 = fmaxf(tmax0, fmaxf(s[j][0], s[j][1]));
            tmax1 = fmaxf(tmax1, fmaxf(s[j][2], s[j][3]));
        }
        tmax0 = fmaxf(tmax0, __shfl_xor_sync(0xffffffffu, tmax0, 1));
        tmax0 = fmaxf(tmax0, __shfl_xor_sync(0xffffffffu, tmax0, 2));
        tmax1 = fmaxf(tmax1, __shfl_xor_sync(0xffffffffu, tmax1, 1));
        tmax1 = fmaxf(tmax1, __shfl_xor_sync(0xffffffffu, tmax1, 2));

        float nm0 = fmaxf(mrow0, tmax0), nm1 = fmaxf(mrow1, tmax1);
        float corr0 = __expf(mrow0 - nm0), corr1 = __expf(mrow1 - nm1);
        mrow0 = nm0; mrow1 = nm1;
#pragma unroll
        for (int j = 0; j < 8; ++j) {
            oacc[j][0] *= corr0; oacc[j][1] *= corr0;
            oacc[j][2] *= corr1; oacc[j][3] *= corr1;
        }

        float ps0 = 0.0f, ps1 = 0.0f;
        uint32_t aH[4][4], aL[4][4];
#pragma unroll
        for (int j = 0; j < 8; ++j) {
            float p0 = __expf(s[j][0] - nm0), p1 = __expf(s[j][1] - nm0);
            float p2 = __expf(s[j][2] - nm1), p3 = __expf(s[j][3] - nm1);
            ps0 += p0 + p1; ps1 += p2 + p3;
            __nv_bfloat16 h0 = __float2bfloat16(p0), h1 = __float2bfloat16(p1);
            __nv_bfloat16 h2 = __float2bfloat16(p2), h3 = __float2bfloat16(p3);
            const int jp = j >> 1, sel = (j & 1) * 2;
            aH[jp][sel + 0] = pkbf2(__bfloat162float(h0), __bfloat162float(h1));
            aH[jp][sel + 1] = pkbf2(__bfloat162float(h2), __bfloat162float(h3));
            aL[jp][sel + 0] = pkbf2(p0 - __bfloat162float(h0), p1 - __bfloat162float(h1));
            aL[jp][sel + 1] = pkbf2(p2 - __bfloat162float(h2), p3 - __bfloat162float(h3));
        }
        ps0 += __shfl_xor_sync(0xffffffffu, ps0, 1);
        ps0 += __shfl_xor_sync(0xffffffffu, ps0, 2);
        ps1 += __shfl_xor_sync(0xffffffffu, ps1, 1);
        ps1 += __shfl_xor_sync(0xffffffffu, ps1, 2);
        lrow0 = lrow0 * corr0 + ps0;
        lrow1 = lrow1 * corr1 + ps1;

#pragma unroll
        for (int jd = 0; jd < 8; ++jd)
#pragma unroll
            for (int ks = 0; ks < 4; ++ks) {
                uint32_t vh2[2], vl2[2];
                uint32_t ad = ((16 * ks + (lane & 15)) * ASTR + 8 * jd) * 2;
                ldsm_x2t(vh2, vhb + ad);
                ldsm_x2t(vl2, vlb + ad);
                mma16816(oacc[jd], aH[ks], vh2);
                mma16816(oacc[jd], aH[ks], vl2);
                mma16816(oacc[jd], aL[ks], vh2);
            }
    }

    const float inv0 = 1.0f / lrow0, inv1 = 1.0f / lrow1;
    const int er = lane >> 2, ec = (lane & 3) * 2;
    const size_t r0o = (rowbase + q0 + wq + er) * NQKV + coff;
    const size_t r1o = r0o + (size_t)8 * NQKV;
#pragma unroll
    for (int jd = 0; jd < 8; ++jd) {
        const int n = 8 * jd + ec;
        float v0 = oacc[jd][0] * inv0, v1 = oacc[jd][1] * inv0;
        float v2 = oacc[jd][2] * inv1, v3 = oacc[jd][3] * inv1;
        __nv_bfloat16 h0 = __float2bfloat16(v0), h1 = __float2bfloat16(v1);
        __nv_bfloat16 h2 = __float2bfloat16(v2), h3 = __float2bfloat16(v3);
        *(__nv_bfloat162*)&AOh[r0o + n] = __halves2bfloat162(h0, h1);
        *(__nv_bfloat162*)&AOh[r1o + n] = __halves2bfloat162(h2, h3);
        __nv_bfloat16 l0 = __float2bfloat16(v0 - __bfloat162float(h0));
        __nv_bfloat16 l1 = __float2bfloat16(v1 - __bfloat162float(h1));
        __nv_bfloat16 l2 = __float2bfloat16(v2 - __bfloat162float(h2));
        __nv_bfloat16 l3 = __float2bfloat16(v3 - __bfloat162float(h3));
        *(__nv_bfloat162*)&AOl[r0o + n] = __halves2bfloat162(l0, l1);
        *(__nv_bfloat162*)&AOl[r1o + n] = __halves2bfloat162(l2, l3);
    }
}

// -------------------- launch ---------------------------------------------------
extern "C" void kernel_launch(void* const* d_in, const int* in_sizes, int n_in,
                              void* d_out, int out_size) {
    const float* x  = (const float*)d_in[0];
    const float* Wq = (const float*)d_in[1];
    const float* bq = (const float*)d_in[2];
    const float* Wk = (const float*)d_in[3];
    const float* bk = (const float*)d_in[4];
    const float* Wv = (const float*)d_in[5];
    const float* bv = (const float*)d_in[6];
    const float* Wo = (const float*)d_in[7];
    const float* bo = (const float*)d_in[8];
    float* out = (float*)d_out;

    __nv_bfloat16 *xh, *xl, *qkvh, *qkvl, *aoh, *aol, *wch, *wcl, *woh, *wol;
    float* bcat;
    cudaGetSymbolAddress((void**)&xh,   g_xh);   cudaGetSymbolAddress((void**)&xl,   g_xl);
    cudaGetSymbolAddress((void**)&qkvh, g_qkvh); cudaGetSymbolAddress((void**)&qkvl, g_qkvl);
    cudaGetSymbolAddress((void**)&aoh,  g_aoh);  cudaGetSymbolAddress((void**)&aol,  g_aol);
    cudaGetSymbolAddress((void**)&wch,  g_wch);  cudaGetSymbolAddress((void**)&wcl,  g_wcl);
    cudaGetSymbolAddress((void**)&woh,  g_woh);  cudaGetSymbolAddress((void**)&wol,  g_wol);
    cudaGetSymbolAddress((void**)&bcat, g_bcat);

    cudaFuncSetAttribute(gemm_bf16x3<0>, cudaFuncAttributeMaxDynamicSharedMemorySize, GSM_TOTAL);
    cudaFuncSetAttribute(gemm_bf16x3<3>, cudaFuncAttributeMaxDynamicSharedMemorySize, GSM_TOTAL);

    // 1) split x into bf16 hi/lo; bias concat
    split_kernel<<<(NTOK * DMODEL / 2 + 255) / 256, 256>>>(x, xh, xl, NTOK * DMODEL / 2);
    bias_cat<<<(NCAT + 255) / 256, 256>>>(bq, bk, bv, bcat);

    // 2) transpose+split weights into concatenated buffer; Wo separately.
    dim3 tb(32, 8);
    transpose_split3<<<dim3(NQKV / 32, DMODEL / 32, 3), tb>>>(
        Wq, wch, wcl,
        Wk, wch + (size_t)512 * DMODEL,  wcl + (size_t)512 * DMODEL,
        Wv, wch + (size_t)1024 * DMODEL, wcl + (size_t)1024 * DMODEL,
        DMODEL, NQKV);
    transpose_split3<<<dim3(DMODEL / 32, NQKV / 32, 1), tb>>>(
        Wo, woh, wol, nullptr, nullptr, nullptr, nullptr, nullptr, nullptr, NQKV, DMODEL);

    // 3) fused QKV projection (mixed precision): Q,K tiles 1-product, V tiles 3
    dim3 gq(NCAT / 128, NTOK / 128);
    gemm_bf16x3<3><<<gq, 512, GSM_TOTAL>>>(xh, xl, wch, wcl, bcat,
                                           nullptr, qkvh, qkvl, DMODEL, NCAT);

    // 4) HMMA flash attention -> AO hi/lo
    dim3 ga(SEQ / 64, NHEAD, 8);
    attn_mma<<<ga, 128>>>(qkvh, qkvl, aoh, aol);

    // 5) output projection (fp32 out, bf16x3): [8192,512] @ [1024,512]^T + bo
    dim3 go(DMODEL / 128, NTOK / 128);
    gemm_bf16x3<0><<<go, 512, GSM_TOTAL>>>(aoh, aol, woh, wol, bo, out,
                                           nullptr, nullptr, NQKV, DMODEL);
}

// round 16
// speedup vs baseline: 1.4718x; 1.4718x over previous
#include <cuda_runtime.h>
#include <cuda_bf16.h>
#include <cuda_fp16.h>
#include <cstdint>

#define NTOK   8192     // 8 * 1024 tokens
#define DMODEL 1024
#define NQKV   512      // H * D_K
#define NQK    1024     // Q|K concatenated
#define NCAT   1536     // Q|K|V logical width in fused GEMM
#define SEQ    1024
#define NHEAD  8
#define DHEAD  64

// -------------------- scratch (device globals: allocation-guard safe) ----------
__device__ __nv_bfloat16 g_xh[NTOK * DMODEL], g_xl[NTOK * DMODEL];
__device__ __half        g_xf[NTOK * DMODEL];
__device__ __nv_bfloat16 g_qkb[NTOK * NQK];      // Q|K bf16
__device__ __half        g_vf[NTOK * NQKV];      // V fp16
__device__ __nv_bfloat16 g_aoh[NTOK * NQKV], g_aol[NTOK * NQKV];
__device__ __nv_bfloat16 g_wqkh[NQK * DMODEL], g_wqkl[NQK * DMODEL];
__device__ __half        g_wvf[NQKV * DMODEL];
__device__ __nv_bfloat16 g_woh[DMODEL * NQKV], g_wol[DMODEL * NQKV];
__device__ float g_bcat[NCAT];

extern __shared__ unsigned char dynsmem[];

// -------------------- PTX helpers (base-target sm_80+ instructions) ------------
__device__ __forceinline__ uint32_t smem_to_u32(const void* p) {
    uint32_t a;
    asm("{ .reg .u64 t; cvta.to.shared.u64 t, %1; cvt.u32.u64 %0, t; }"
        : "=r"(a) : "l"(p));
    return a;
}
__device__ __forceinline__ void cp16(uint32_t dst, const void* src) {
    asm volatile("cp.async.ca.shared.global [%0], [%1], 16;"
                 :: "r"(dst), "l"(src) : "memory");
}
#define CP_COMMIT() asm volatile("cp.async.commit_group;" ::: "memory")
#define CP_WAIT1()  asm volatile("cp.async.wait_group 1;" ::: "memory")
#define CP_WAIT0()  asm volatile("cp.async.wait_group 0;" ::: "memory")

__device__ __forceinline__ void ldsm_x4(uint32_t* r, uint32_t addr) {
    asm volatile("ldmatrix.sync.aligned.m8n8.x4.shared.b16 {%0,%1,%2,%3}, [%4];"
                 : "=r"(r[0]), "=r"(r[1]), "=r"(r[2]), "=r"(r[3]) : "r"(addr));
}
__device__ __forceinline__ void ldsm_x2(uint32_t* r, uint32_t addr) {
    asm volatile("ldmatrix.sync.aligned.m8n8.x2.shared.b16 {%0,%1}, [%2];"
                 : "=r"(r[0]), "=r"(r[1]) : "r"(addr));
}
__device__ __forceinline__ void ldsm_x2t(uint32_t* r, uint32_t addr) {
    asm volatile("ldmatrix.sync.aligned.m8n8.x2.trans.shared.b16 {%0,%1}, [%2];"
                 : "=r"(r[0]), "=r"(r[1]) : "r"(addr));
}
// bf16 MMA
__device__ __forceinline__ void mma16816(float* c, const uint32_t* a, const uint32_t* b) {
    asm volatile("mma.sync.aligned.m16n8k16.row.col.f32.bf16.bf16.f32 "
                 "{%0,%1,%2,%3}, {%4,%5,%6,%7}, {%8,%9}, {%0,%1,%2,%3};"
                 : "+f"(c[0]), "+f"(c[1]), "+f"(c[2]), "+f"(c[3])
                 : "r"(a[0]), "r"(a[1]), "r"(a[2]), "r"(a[3]),
                   "r"(b[0]), "r"(b[1]));
}
// fp16 MMA
__device__ __forceinline__ void mma16816h(float* c, const uint32_t* a, const uint32_t* b) {
    asm volatile("mma.sync.aligned.m16n8k16.row.col.f32.f16.f16.f32 "
                 "{%0,%1,%2,%3}, {%4,%5,%6,%7}, {%8,%9}, {%0,%1,%2,%3};"
                 : "+f"(c[0]), "+f"(c[1]), "+f"(c[2]), "+f"(c[3])
                 : "r"(a[0]), "r"(a[1]), "r"(a[2]), "r"(a[3]),
                   "r"(b[0]), "r"(b[1]));
}
__device__ __forceinline__ uint32_t pkhf2(float lo, float hi) {
    __half2 t = __floats2half2_rn(lo, hi);
    return reinterpret_cast<uint32_t&>(t);
}

// -------------------- pre-pass: split fp32 -> bf16 hi/lo + fp16 ----------------
__global__ void split3_kernel(const float* __restrict__ src,
                              __nv_bfloat16* __restrict__ hi,
                              __nv_bfloat16* __restrict__ lo,
                              __half* __restrict__ hf, int n2) {
    int i = blockIdx.x * blockDim.x + threadIdx.x;
    if (i < n2) {
        float2 v = ((const float2*)src)[i];
        __nv_bfloat16 h0 = __float2bfloat16(v.x);
        __nv_bfloat16 h1 = __float2bfloat16(v.y);
        __nv_bfloat16 l0 = __float2bfloat16(v.x - __bfloat162float(h0));
        __nv_bfloat16 l1 = __float2bfloat16(v.y - __bfloat162float(h1));
        ((__nv_bfloat162*)hi)[i] = __halves2bfloat162(h0, h1);
        ((__nv_bfloat162*)lo)[i] = __halves2bfloat162(l0, l1);
        ((__half2*)hf)[i] = __floats2half2_rn(v.x, v.y);
    }
}

// -------------------- pre-pass: bias concat ------------------------------------
__global__ void bias_cat(const float* __restrict__ bq, const float* __restrict__ bk,
                         const float* __restrict__ bv, float* __restrict__ bc) {
    int i = blockIdx.x * blockDim.x + threadIdx.x;
    if (i < NCAT)
        bc[i] = (i < 512) ? bq[i] : (i < 1024) ? bk[i - 512] : bv[i - 1024];
}

// -------------------- pre-pass: W[K,N] fp32 -> Wt[N,K] ------------------------
// z slice == fpz -> write fp16 into (half*)Th only; else bf16 hi/lo.
__global__ void transpose_split3(const float* __restrict__ W0, __nv_bfloat16* __restrict__ T0h,
                                 __nv_bfloat16* __restrict__ T0l,
                                 const float* __restrict__ W1, __nv_bfloat16* __restrict__ T1h,
                                 __nv_bfloat16* __restrict__ T1l,
                                 const float* __restrict__ W2, __nv_bfloat16* __restrict__ T2h,
                                 __nv_bfloat16* __restrict__ T2l,
                                 int Kd, int Nd, int fpz) {
    __shared__ float t[32][33];
    const float* W = (blockIdx.z == 0) ? W0 : (blockIdx.z == 1) ? W1 : W2;
    __nv_bfloat16* Th = (blockIdx.z == 0) ? T0h : (blockIdx.z == 1) ? T1h : T2h;
    __nv_bfloat16* Tl = (blockIdx.z == 0) ? T0l : (blockIdx.z == 1) ? T1l : T2l;
    const bool isf = ((int)blockIdx.z == fpz);
    int k0 = blockIdx.y * 32, n0 = blockIdx.x * 32;
    for (int i = threadIdx.y; i < 32; i += 8)
        t[i][threadIdx.x] = W[(size_t)(k0 + i) * Nd + n0 + threadIdx.x];
    __syncthreads();
    for (int i = threadIdx.y; i < 32; i += 8) {
        float v = t[threadIdx.x][i];
        size_t o = (size_t)(n0 + i) * Kd + k0 + threadIdx.x;
        if (isf) {
            ((__half*)Th)[o] = __float2half(v);
        } else {
            __nv_bfloat16 h = __float2bfloat16(v);
            Th[o] = h;
            Tl[o] = __float2bfloat16(v - __bfloat162float(h));
        }
    }
}

// -------------------- mixed-precision HMMA GEMM (R13 8-warp config) ------------
// CTA tile 128x128, BK=32, 256 threads, 8 warps of 64x32, double-buffered.
// OM=0: out-proj — bf16x3 (3 products), fp32 out.
// OM=3: fused QKV — n0<1024: 1-product bf16 -> Q|K bf16 out (stride NQK);
//                   n0>=1024: 1-product fp16 -> V fp16 out (stride NQKV).
#define GASTRIDE   40                       // 16-bit elems per smem row
#define GMAT_BYTES (128 * GASTRIDE * 2)     // 10240 B per matrix tile
#define GSTAGE     (4 * GMAT_BYTES)         // 40960 B
#define GSM_TOTAL  (2 * GSTAGE)             // 81920 B

template <int OM>
__global__ __launch_bounds__(256)
void gemm_mp(const uint16_t* __restrict__ Ah, const uint16_t* __restrict__ Al,
             const uint16_t* __restrict__ Af,
             const uint16_t* __restrict__ Bh, const uint16_t* __restrict__ Bl,
             const uint16_t* __restrict__ Bf,
             const float* __restrict__ bias, float* __restrict__ Cf,
             __nv_bfloat16* __restrict__ Cb, __half* __restrict__ Cv,
             int K, int N) {
    const uint32_t smem_base = smem_to_u32(dynsmem);
    const int tid  = threadIdx.x;
    const int wid  = tid >> 5, lane = tid & 31;
    const int m0 = blockIdx.y * 128, n0 = blockIdx.x * 128;
    const bool isV = (OM == 3) && (n0 >= NQK);

    // ---- loader mapping: 64 threads per matrix, 2 rows each, 4x16B per row ----
    const int mat = tid >> 6;           // 0=A 1=Al 2=B 3=Bl
    const int rr  = tid & 63;
    const uint16_t* mats[4] = { isV ? Af : Ah, Al, isV ? Bf : Bh, Bl };
    const int brow = (mat < 2) ? m0 : (isV ? n0 - NQK : n0);
    const uint16_t* gsrc = mats[mat] + (size_t)brow * K;
    const uint32_t sdst = smem_base + mat * GMAT_BYTES;
    const bool ldme = (OM == 0) || mat == 0 || mat == 2;

    // ---- compute mapping: 8 warps = 2 (m) x 4 (n), 64x32 each ----------------
    const int wm = (wid & 1) * 64;
    const int wn = (wid >> 1) * 32;
    const int aRowOff = lane & 15;
    const int aColOff = (lane & 16) ? 8 : 0;
    const int bRowOff = lane & 7;
    const int bColOff = (lane & 8) ? 8 : 0;

    float acc[4][4][4];
#pragma unroll
    for (int i = 0; i < 4; i++)
#pragma unroll
        for (int j = 0; j < 4; j++)
#pragma unroll
            for (int c = 0; c < 4; c++) acc[i][j][c] = 0.0f;

    const int nstage = K >> 5;
    if (ldme) {
#pragma unroll
        for (int h = 0; h < 2; ++h) {
            int row = rr + h * 64;
            const uint16_t* src = gsrc + (size_t)row * K;
            uint32_t d = sdst + row * (GASTRIDE * 2);
#pragma unroll
            for (int c = 0; c < 4; ++c) cp16(d + c * 16, src + c * 8);
        }
    }
    CP_COMMIT();

    for (int s = 0; s < nstage; ++s) {
        if (s + 1 < nstage) {
            const int k0 = (s + 1) << 5;
            const uint32_t boff = ((s + 1) & 1) * GSTAGE;
            if (ldme) {
#pragma unroll
                for (int h = 0; h < 2; ++h) {
                    int row = rr + h * 64;
                    const uint16_t* src = gsrc + (size_t)row * K + k0;
                    uint32_t d = sdst + boff + row * (GASTRIDE * 2);
#pragma unroll
                    for (int c = 0; c < 4; ++c) cp16(d + c * 16, src + c * 8);
                }
            }
            CP_COMMIT();
            CP_WAIT1();
        } else {
            CP_WAIT0();
        }
        __syncthreads();

        const uint32_t sb = smem_base + (s & 1) * GSTAGE;
        const uint32_t sbB = sb + 2 * GMAT_BYTES;
        if (OM == 0) {          // 3-product bf16
#pragma unroll
            for (int kc = 0; kc < 32; kc += 16) {
                uint32_t ah[4][4], al[4][4], bh[4][2], bl[4][2];
#pragma unroll
                for (int i = 0; i < 4; ++i) {
                    uint32_t addr = sb + (wm + 16 * i + aRowOff) * (GASTRIDE * 2)
                                       + (kc + aColOff) * 2;
                    ldsm_x4(ah[i], addr);
                    ldsm_x4(al[i], addr + GMAT_BYTES);
                }
#pragma unroll
                for (int j = 0; j < 4; ++j) {
                    uint32_t addr = sbB + (wn + 8 * j + bRowOff) * (GASTRIDE * 2)
                                        + (kc + bColOff) * 2;
                    ldsm_x2(bh[j], addr);
                    ldsm_x2(bl[j], addr + GMAT_BYTES);
                }
#pragma unroll
                for (int i = 0; i < 4; ++i)
#pragma unroll
                    for (int j = 0; j < 4; ++j) {
                        mma16816(acc[i][j], ah[i], bh[j]);
                        mma16816(acc[i][j], ah[i], bl[j]);
                        mma16816(acc[i][j], al[i], bh[j]);
                    }
            }
        } else if (!isV) {      // 1-product bf16 (Q,K)
#pragma unroll
            for (int kc = 0; kc < 32; kc += 16) {
                uint32_t ah[4][4], bh[4][2];
#pragma unroll
                for (int i = 0; i < 4; ++i)
                    ldsm_x4(ah[i], sb + (wm + 16 * i + aRowOff) * (GASTRIDE * 2)
                                      + (kc + aColOff) * 2);
#pragma unroll
                for (int j = 0; j < 4; ++j)
                    ldsm_x2(bh[j], sbB + (wn + 8 * j + bRowOff) * (GASTRIDE * 2)
                                       + (kc + bColOff) * 2);
#pragma unroll
                for (int i = 0; i < 4; ++i)
#pragma unroll
                    for (int j = 0; j < 4; ++j)
                        mma16816(acc[i][j], ah[i], bh[j]);
            }
        } else {                // 1-product fp16 (V)
#pragma unroll
            for (int kc = 0; kc < 32; kc += 16) {
                uint32_t ah[4][4], bh[4][2];
#pragma unroll
                for (int i = 0; i < 4; ++i)
                    ldsm_x4(ah[i], sb + (wm + 16 * i + aRowOff) * (GASTRIDE * 2)
                                      + (kc + aColOff) * 2);
#pragma unroll
                for (int j = 0; j < 4; ++j)
                    ldsm_x2(bh[j], sbB + (wn + 8 * j + bRowOff) * (GASTRIDE * 2)
                                       + (kc + bColOff) * 2);
#pragma unroll
                for (int i = 0; i < 4; ++i)
#pragma unroll
                    for (int j = 0; j < 4; ++j)
                        mma16816h(acc[i][j], ah[i], bh[j]);
            }
        }
        __syncthreads();
    }

    // ---- epilogue ----
    const int er = lane >> 2;
    const int ec = (lane & 3) * 2;
#pragma unroll
    for (int j = 0; j < 4; ++j) {
        const int n = n0 + wn + 8 * j + ec;
        const float b0 = bias[n], b1 = bias[n + 1];
#pragma unroll
        for (int i = 0; i < 4; ++i) {
            const int m = m0 + wm + 16 * i + er;
            float v0 = acc[i][j][0] + b0, v1 = acc[i][j][1] + b1;
            float v2 = acc[i][j][2] + b0, v3 = acc[i][j][3] + b1;
            if (OM == 0) {
                *(float2*)(Cf + (size_t)m * N + n)       = make_float2(v0, v1);
                *(float2*)(Cf + (size_t)(m + 8) * N + n) = make_float2(v2, v3);
            } else if (!isV) {
                *(__nv_bfloat162*)(Cb + (size_t)m * NQK + n) =
                    __halves2bfloat162(__float2bfloat16(v0), __float2bfloat16(v1));
                *(__nv_bfloat162*)(Cb + (size_t)(m + 8) * NQK + n) =
                    __halves2bfloat162(__float2bfloat16(v2), __float2bfloat16(v3));
            } else {
                const int nv = n - NQK;
                *(__half2*)(Cv + (size_t)m * NQKV + nv)       = __floats2half2_rn(v0, v1);
                *(__half2*)(Cv + (size_t)(m + 8) * NQKV + nv) = __floats2half2_rn(v2, v3);
            }
        }
    }
}

// -------------------- HMMA flash attention: bf16 S, fp16 PV --------------------
#define ASTR 72   // 16-bit elems per smem row

__global__ __launch_bounds__(128)
void attn_mma(const __nv_bfloat16* __restrict__ QKb, const __half* __restrict__ Vf,
              __nv_bfloat16* __restrict__ AOh, __nv_bfloat16* __restrict__ AOl) {
    __shared__ __align__(16) __nv_bfloat16 Qs[64 * ASTR];
    __shared__ __align__(16) __nv_bfloat16 Ks[64 * ASTR];
    __shared__ __align__(16) __half        Vs[64 * ASTR];

    const int tid = threadIdx.x, wid = tid >> 5, lane = tid & 31;
    const int q0 = blockIdx.x * 64, h = blockIdx.y, b = blockIdx.z;
    const size_t rowbase = (size_t)b * SEQ;
    const int coff = h * DHEAD;

    const __nv_bfloat16* Qp = QKb + coff;          // stride NQK
    const __nv_bfloat16* Kp = QKb + 512 + coff;    // stride NQK
    const __half*        Vp = Vf + coff;           // stride NQKV

    const int lr = tid >> 1, lc = (tid & 1) * 32;
    {
        const __nv_bfloat16* src = Qp + (rowbase + q0 + lr) * NQK + lc;
#pragma unroll
        for (int c = 0; c < 4; ++c)
            *(uint4*)&Qs[lr * ASTR + lc + 8 * c] = *(const uint4*)(src + 8 * c);
    }
    __syncthreads();

    const uint32_t qbase = smem_to_u32(Qs), kbase = smem_to_u32(Ks);
    const uint32_t vbase = smem_to_u32(Vs);
    const int wq = wid * 16;

    uint32_t qf[4][4];
#pragma unroll
    for (int ks = 0; ks < 4; ++ks)
        ldsm_x4(qf[ks], qbase + ((wq + (lane & 15)) * ASTR + ks * 16
                                 + ((lane & 16) ? 8 : 0)) * 2);

    float oacc[8][4];
#pragma unroll
    for (int j = 0; j < 8; ++j)
#pragma unroll
        for (int c = 0; c < 4; ++c) oacc[j][c] = 0.0f;
    float mrow0 = -1e30f, mrow1 = -1e30f, lrow0 = 0.0f, lrow1 = 0.0f;

    for (int kv0 = 0; kv0 < SEQ; kv0 += 64) {
        __syncthreads();
        {
            const size_t krow = (rowbase + kv0 + lr) * NQK + lc;
            const size_t vrow = (rowbase + kv0 + lr) * NQKV + lc;
            const int so = lr * ASTR + lc;
#pragma unroll
            for (int c = 0; c < 4; ++c) {
                *(uint4*)&Ks[so + 8 * c] = *(const uint4*)(Kp + krow + 8 * c);
                *(uint4*)&Vs[so + 8 * c] = *(const uint4*)(Vp + vrow + 8 * c);
            }
        }
        __syncthreads();

        // ---- S = Q @ K^T (bf16) ----
        float s[8][4];
#pragma unroll
        for (int j = 0; j < 8; ++j)
#pragma unroll
            for (int c = 0; c < 4; ++c) s[j][c] = 0.0f;
#pragma unroll
        for (int ks = 0; ks < 4; ++ks)
#pragma unroll
            for (int j = 0; j < 8; ++j) {
                uint32_t kf[2];
                ldsm_x2(kf, kbase + ((8 * j + (lane & 7)) * ASTR + ks * 16
                                     + ((lane & 8) ? 8 : 0)) * 2);
                mma16816(s[j], qf[ks], kf);
            }

        // ---- register softmax ----
        float tmax0 = -1e30f, tmax1 = -1e30f;
#pragma unroll
        for (int j = 0; j < 8; ++j) {
            s[j][0] *= 0.125f; s[j][1] *= 0.125f; s[j][2] *= 0.125f; s[j][3] *= 0.125f;
            tmax0 = fmaxf(tmax0, fmaxf(s[j][0], s[j][1]));
            tmax1 = fmaxf(tmax1, fmaxf(s[j][2], s[j][3]));
        }
        tmax0 = fmaxf(tmax0, __shfl_xor_sync(0xffffffffu, tmax0, 1));
        tmax0 = fmaxf(tmax0, __shfl_xor_sync(0xffffffffu, tmax0, 2));
        tmax1 = fmaxf(tmax1, __shfl_xor_sync(0xffffffffu, tmax1, 1));
        tmax1 = fmaxf(tmax1, __shfl_xor_sync(0xffffffffu, tmax1, 2));

        float nm0 = fmaxf(mrow0, tmax0), nm1 = fmaxf(mrow1, tmax1);
        float corr0 = __expf(mrow0 - nm0), corr1 = __expf(mrow1 - nm1);
        mrow0 = nm0; mrow1 = nm1;
#pragma unroll
        for (int j = 0; j < 8; ++j) {
            oacc[j][0] *= corr0; oacc[j][1] *= corr0;
            oacc[j][2] *= corr1; oacc[j][3] *= corr1;
        }

        float ps0 = 0.0f, ps1 = 0.0f;
        uint32_t aH[4][4];     // P fragments in fp16
#pragma unroll
        for (int j = 0; j < 8; ++j) {
            float p0 = __expf(s[j][0] - nm0), p1 = __expf(s[j][1] - nm0);
            float p2 = __expf(s[j][2] - nm1), p3 = __expf(s[j][3] - nm1);
            ps0 += p0 + p1; ps1 += p2 + p3;
            const int jp = j >> 1, sel = (j & 1) * 2;
            aH[jp][sel + 0] = pkhf2(p0, p1);
            aH[jp][sel + 1] = pkhf2(p2, p3);
        }
        ps0 += __shfl_xor_sync(0xffffffffu, ps0, 1);
        ps0 += __shfl_xor_sync(0xffffffffu, ps0, 2);
        ps1 += __shfl_xor_sync(0xffffffffu, ps1, 1);
        ps1 += __shfl_xor_sync(0xffffffffu, ps1, 2);
        lrow0 = lrow0 * corr0 + ps0;
        lrow1 = lrow1 * corr1 + ps1;

        // ---- O += P @ V (fp16, single product) ----
#pragma unroll
        for (int jd = 0; jd < 8; ++jd)
#pragma unroll
            for (int ks = 0; ks < 4; ++ks) {
                uint32_t v2[2];
                ldsm_x2t(v2, vbase + ((16 * ks + (lane & 15)) * ASTR + 8 * jd) * 2);
                mma16816h(oacc[jd], aH[ks], v2);
            }
    }

    const float inv0 = 1.0f / lrow0, inv1 = 1.0f / lrow1;
    const int er = lane >> 2, ec = (lane & 3) * 2;
    const size_t r0o = (rowbase + q0 + wq + er) * NQKV + coff;
    const size_t r1o = r0o + (size_t)8 * NQKV;
#pragma unroll
    for (int jd = 0; jd < 8; ++jd) {
        const int n = 8 * jd + ec;
        float v0 = oacc[jd][0] * inv0, v1 = oacc[jd][1] * inv0;
        float v2 = oacc[jd][2] * inv1, v3 = oacc[jd][3] * inv1;
        __nv_bfloat16 h0 = __float2bfloat16(v0), h1 = __float2bfloat16(v1);
        __nv_bfloat16 h2 = __float2bfloat16(v2), h3 = __float2bfloat16(v3);
        *(__nv_bfloat162*)&AOh[r0o + n] = __halves2bfloat162(h0, h1);
        *(__nv_bfloat162*)&AOh[r1o + n] = __halves2bfloat162(h2, h3);
        __nv_bfloat16 l0 = __float2bfloat16(v0 - __bfloat162float(h0));
        __nv_bfloat16 l1 = __float2bfloat16(v1 - __bfloat162float(h1));
        __nv_bfloat16 l2 = __float2bfloat16(v2 - __bfloat162float(h2));
        __nv_bfloat16 l3 = __float2bfloat16(v3 - __bfloat162float(h3));
        *(__nv_bfloat162*)&AOl[r0o + n] = __halves2bfloat162(l0, l1);
        *(__nv_bfloat162*)&AOl[r1o + n] = __halves2bfloat162(l2, l3);
    }
}

// -------------------- launch ---------------------------------------------------
extern "C" void kernel_launch(void* const* d_in, const int* in_sizes, int n_in,
                              void* d_out, int out_size) {
    const float* x  = (const float*)d_in[0];
    const float* Wq = (const float*)d_in[1];
    const float* bq = (const float*)d_in[2];
    const float* Wk = (const float*)d_in[3];
    const float* bk = (const float*)d_in[4];
    const float* Wv = (const float*)d_in[5];
    const float* bv = (const float*)d_in[6];
    const float* Wo = (const float*)d_in[7];
    const float* bo = (const float*)d_in[8];
    float* out = (float*)d_out;

    __nv_bfloat16 *xh, *xl, *qkb, *aoh, *aol, *wqkh, *wqkl, *woh, *wol;
    __half *xf, *vf, *wvf;
    float* bcat;
    cudaGetSymbolAddress((void**)&xh,   g_xh);   cudaGetSymbolAddress((void**)&xl,   g_xl);
    cudaGetSymbolAddress((void**)&xf,   g_xf);
    cudaGetSymbolAddress((void**)&qkb,  g_qkb);  cudaGetSymbolAddress((void**)&vf,   g_vf);
    cudaGetSymbolAddress((void**)&aoh,  g_aoh);  cudaGetSymbolAddress((void**)&aol,  g_aol);
    cudaGetSymbolAddress((void**)&wqkh, g_wqkh); cudaGetSymbolAddress((void**)&wqkl, g_wqkl);
    cudaGetSymbolAddress((void**)&wvf,  g_wvf);
    cudaGetSymbolAddress((void**)&woh,  g_woh);  cudaGetSymbolAddress((void**)&wol,  g_wol);
    cudaGetSymbolAddress((void**)&bcat, g_bcat);

    cudaFuncSetAttribute(gemm_mp<0>, cudaFuncAttributeMaxDynamicSharedMemorySize, GSM_TOTAL);
    cudaFuncSetAttribute(gemm_mp<3>, cudaFuncAttributeMaxDynamicSharedMemorySize, GSM_TOTAL);

    // 1) split x -> bf16 hi/lo + fp16; bias concat
    split3_kernel<<<(NTOK * DMODEL / 2 + 255) / 256, 256>>>(x, xh, xl, xf, NTOK * DMODEL / 2);
    bias_cat<<<(NCAT + 255) / 256, 256>>>(bq, bk, bv, bcat);

    // 2) transpose weights: Wq,Wk -> bf16 h/l; Wv -> fp16; Wo -> bf16 h/l
    dim3 tb(32, 8);
    transpose_split3<<<dim3(NQKV / 32, DMODEL / 32, 3), tb>>>(
        Wq, wqkh, wqkl,
        Wk, wqkh + (size_t)512 * DMODEL, wqkl + (size_t)512 * DMODEL,
        Wv, (__nv_bfloat16*)wvf, nullptr,
        DMODEL, NQKV, /*fpz=*/2);
    transpose_split3<<<dim3(DMODEL / 32, NQKV / 32, 1), tb>>>(
        Wo, woh, wol, nullptr, nullptr, nullptr, nullptr, nullptr, nullptr,
        NQKV, DMODEL, /*fpz=*/-1);

    // 3) fused QKV projection: Q,K 1-prod bf16 -> qkb; V 1-prod fp16 -> vf
    dim3 gq(NCAT / 128, NTOK / 128);
    gemm_mp<3><<<gq, 256, GSM_TOTAL>>>(
        (const uint16_t*)xh, (const uint16_t*)xl, (const uint16_t*)xf,
        (const uint16_t*)wqkh, (const uint16_t*)wqkl, (const uint16_t*)wvf,
        bcat, nullptr, qkb, vf, DMODEL, NCAT);

    // 4) flash attention: bf16 S + fp16 PV -> AO bf16 hi/lo
    dim3 ga(SEQ / 64, NHEAD, 8);
    attn_mma<<<ga, 128>>>(qkb, vf, aoh, aol);

    // 5) output projection (bf16x3, fp32 out): [8192,512] @ [1024,512]^T + bo
    dim3 go(DMODEL / 128, NTOK / 128);
    gemm_mp<0><<<go, 256, GSM_TOTAL>>>(
        (const uint16_t*)aoh, (const uint16_t*)aol, nullptr,
        (const uint16_t*)woh, (const uint16_t*)wol, nullptr,
        bo, out, nullptr, nullptr, NQKV, DMODEL);
}

// round 17
// speedup vs baseline: 1.7286x; 1.1745x over previous
#include <cuda_runtime.h>
#include <cuda_bf16.h>
#include <cuda_fp16.h>
#include <cstdint>

#define NTOK   8192     // 8 * 1024 tokens
#define DMODEL 1024
#define NQKV   512      // H * D_K
#define NQK    1024     // Q|K concatenated
#define NCAT   1536     // Q|K|V logical width in fused GEMM
#define SEQ    1024
#define NHEAD  8
#define DHEAD  64

// -------------------- scratch (device globals: allocation-guard safe) ----------
__device__ __nv_bfloat16 g_xh[NTOK * DMODEL], g_xl[NTOK * DMODEL];
__device__ __half        g_xf[NTOK * DMODEL];
__device__ __nv_bfloat16 g_qkb[NTOK * NQK];      // Q|K bf16
__device__ __half        g_vf[NTOK * NQKV];      // V fp16
__device__ __half        g_aof[NTOK * NQKV];     // attention out, fp16
__device__ __nv_bfloat16 g_wqkh[NQK * DMODEL], g_wqkl[NQK * DMODEL];
__device__ __half        g_wvf[NQKV * DMODEL];
__device__ __half        g_wof[DMODEL * NQKV];
__device__ float g_bcat[NCAT];

extern __shared__ unsigned char dynsmem[];

// -------------------- PTX helpers (base-target sm_80+ instructions) ------------
__device__ __forceinline__ uint32_t smem_to_u32(const void* p) {
    uint32_t a;
    asm("{ .reg .u64 t; cvta.to.shared.u64 t, %1; cvt.u32.u64 %0, t; }"
        : "=r"(a) : "l"(p));
    return a;
}
__device__ __forceinline__ void cp16(uint32_t dst, const void* src) {
    asm volatile("cp.async.ca.shared.global [%0], [%1], 16;"
                 :: "r"(dst), "l"(src) : "memory");
}
#define CP_COMMIT() asm volatile("cp.async.commit_group;" ::: "memory")
#define CP_WAIT1()  asm volatile("cp.async.wait_group 1;" ::: "memory")
#define CP_WAIT0()  asm volatile("cp.async.wait_group 0;" ::: "memory")

__device__ __forceinline__ void ldsm_x4(uint32_t* r, uint32_t addr) {
    asm volatile("ldmatrix.sync.aligned.m8n8.x4.shared.b16 {%0,%1,%2,%3}, [%4];"
                 : "=r"(r[0]), "=r"(r[1]), "=r"(r[2]), "=r"(r[3]) : "r"(addr));
}
__device__ __forceinline__ void ldsm_x2(uint32_t* r, uint32_t addr) {
    asm volatile("ldmatrix.sync.aligned.m8n8.x2.shared.b16 {%0,%1}, [%2];"
                 : "=r"(r[0]), "=r"(r[1]) : "r"(addr));
}
__device__ __forceinline__ void ldsm_x2t(uint32_t* r, uint32_t addr) {
    asm volatile("ldmatrix.sync.aligned.m8n8.x2.trans.shared.b16 {%0,%1}, [%2];"
                 : "=r"(r[0]), "=r"(r[1]) : "r"(addr));
}
// bf16 MMA
__device__ __forceinline__ void mma16816(float* c, const uint32_t* a, const uint32_t* b) {
    asm volatile("mma.sync.aligned.m16n8k16.row.col.f32.bf16.bf16.f32 "
                 "{%0,%1,%2,%3}, {%4,%5,%6,%7}, {%8,%9}, {%0,%1,%2,%3};"
                 : "+f"(c[0]), "+f"(c[1]), "+f"(c[2]), "+f"(c[3])
                 : "r"(a[0]), "r"(a[1]), "r"(a[2]), "r"(a[3]),
                   "r"(b[0]), "r"(b[1]));
}
// fp16 MMA
__device__ __forceinline__ void mma16816h(float* c, const uint32_t* a, const uint32_t* b) {
    asm volatile("mma.sync.aligned.m16n8k16.row.col.f32.f16.f16.f32 "
                 "{%0,%1,%2,%3}, {%4,%5,%6,%7}, {%8,%9}, {%0,%1,%2,%3};"
                 : "+f"(c[0]), "+f"(c[1]), "+f"(c[2]), "+f"(c[3])
                 : "r"(a[0]), "r"(a[1]), "r"(a[2]), "r"(a[3]),
                   "r"(b[0]), "r"(b[1]));
}
__device__ __forceinline__ uint32_t pkhf2(float lo, float hi) {
    __half2 t = __floats2half2_rn(lo, hi);
    return reinterpret_cast<uint32_t&>(t);
}

// -------------------- pre-pass: split fp32 -> bf16 hi/lo + fp16 ----------------
__global__ void split3_kernel(const float* __restrict__ src,
                              __nv_bfloat16* __restrict__ hi,
                              __nv_bfloat16* __restrict__ lo,
                              __half* __restrict__ hf, int n2) {
    int i = blockIdx.x * blockDim.x + threadIdx.x;
    if (i < n2) {
        float2 v = ((const float2*)src)[i];
        __nv_bfloat16 h0 = __float2bfloat16(v.x);
        __nv_bfloat16 h1 = __float2bfloat16(v.y);
        __nv_bfloat16 l0 = __float2bfloat16(v.x - __bfloat162float(h0));
        __nv_bfloat16 l1 = __float2bfloat16(v.y - __bfloat162float(h1));
        ((__nv_bfloat162*)hi)[i] = __halves2bfloat162(h0, h1);
        ((__nv_bfloat162*)lo)[i] = __halves2bfloat162(l0, l1);
        ((__half2*)hf)[i] = __floats2half2_rn(v.x, v.y);
    }
}

// -------------------- pre-pass: bias concat ------------------------------------
__global__ void bias_cat(const float* __restrict__ bq, const float* __restrict__ bk,
                         const float* __restrict__ bv, float* __restrict__ bc) {
    int i = blockIdx.x * blockDim.x + threadIdx.x;
    if (i < NCAT)
        bc[i] = (i < 512) ? bq[i] : (i < 1024) ? bk[i - 512] : bv[i - 1024];
}

// -------------------- pre-pass: W[K,N] fp32 -> Wt[N,K] ------------------------
// z slice == fpz -> write fp16 into (half*)Th only; else bf16 hi/lo.
__global__ void transpose_split3(const float* __restrict__ W0, __nv_bfloat16* __restrict__ T0h,
                                 __nv_bfloat16* __restrict__ T0l,
                                 const float* __restrict__ W1, __nv_bfloat16* __restrict__ T1h,
                                 __nv_bfloat16* __restrict__ T1l,
                                 const float* __restrict__ W2, __nv_bfloat16* __restrict__ T2h,
                                 __nv_bfloat16* __restrict__ T2l,
                                 int Kd, int Nd, int fpz) {
    __shared__ float t[32][33];
    const float* W = (blockIdx.z == 0) ? W0 : (blockIdx.z == 1) ? W1 : W2;
    __nv_bfloat16* Th = (blockIdx.z == 0) ? T0h : (blockIdx.z == 1) ? T1h : T2h;
    __nv_bfloat16* Tl = (blockIdx.z == 0) ? T0l : (blockIdx.z == 1) ? T1l : T2l;
    const bool isf = ((int)blockIdx.z == fpz);
    int k0 = blockIdx.y * 32, n0 = blockIdx.x * 32;
    for (int i = threadIdx.y; i < 32; i += 8)
        t[i][threadIdx.x] = W[(size_t)(k0 + i) * Nd + n0 + threadIdx.x];
    __syncthreads();
    for (int i = threadIdx.y; i < 32; i += 8) {
        float v = t[threadIdx.x][i];
        size_t o = (size_t)(n0 + i) * Kd + k0 + threadIdx.x;
        if (isf) {
            ((__half*)Th)[o] = __float2half(v);
        } else {
            __nv_bfloat16 h = __float2bfloat16(v);
            Th[o] = h;
            Tl[o] = __float2bfloat16(v - __bfloat162float(h));
        }
    }
}

// -------------------- mixed-precision HMMA GEMM (R13 8-warp config) ------------
// CTA tile 128x128, BK=32, 256 threads, 8 warps of 64x32, double-buffered.
// OM=1: out-proj — 1-product fp16 (Ah/Bh carry fp16 bits), fp32 out + bias.
// OM=3: fused QKV — n0<1024: 1-product bf16 -> Q|K bf16 out (stride NQK);
//                   n0>=1024: 1-product fp16 -> V fp16 out (stride NQKV).
#define GASTRIDE   40                       // 16-bit elems per smem row
#define GMAT_BYTES (128 * GASTRIDE * 2)     // 10240 B per matrix tile
#define GSTAGE     (4 * GMAT_BYTES)         // 40960 B
#define GSM_TOTAL  (2 * GSTAGE)             // 81920 B

template <int OM>
__global__ __launch_bounds__(256)
void gemm_mp(const uint16_t* __restrict__ Ah, const uint16_t* __restrict__ Al,
             const uint16_t* __restrict__ Af,
             const uint16_t* __restrict__ Bh, const uint16_t* __restrict__ Bl,
             const uint16_t* __restrict__ Bf,
             const float* __restrict__ bias, float* __restrict__ Cf,
             __nv_bfloat16* __restrict__ Cb, __half* __restrict__ Cv,
             int K, int N) {
    const uint32_t smem_base = smem_to_u32(dynsmem);
    const int tid  = threadIdx.x;
    const int wid  = tid >> 5, lane = tid & 31;
    const int m0 = blockIdx.y * 128, n0 = blockIdx.x * 128;
    const bool isV = (OM == 3) && (n0 >= NQK);
    const bool fp1 = (OM == 1) || isV;      // fp16 1-product mainloop

    // ---- loader mapping: 64 threads per matrix, 2 rows each, 4x16B per row ----
    const int mat = tid >> 6;           // 0=A 1=Al 2=B 3=Bl
    const int rr  = tid & 63;
    const uint16_t* mats[4] = { isV ? Af : Ah, Al, isV ? Bf : Bh, Bl };
    const int brow = (mat < 2) ? m0 : (isV ? n0 - NQK : n0);
    const uint16_t* gsrc = mats[mat] + (size_t)brow * K;
    const uint32_t sdst = smem_base + mat * GMAT_BYTES;
    const bool ldme = (mat == 0 || mat == 2);   // Al/Bl never used (1-product paths)

    // ---- compute mapping: 8 warps = 2 (m) x 4 (n), 64x32 each ----------------
    const int wm = (wid & 1) * 64;
    const int wn = (wid >> 1) * 32;
    const int aRowOff = lane & 15;
    const int aColOff = (lane & 16) ? 8 : 0;
    const int bRowOff = lane & 7;
    const int bColOff = (lane & 8) ? 8 : 0;

    float acc[4][4][4];
#pragma unroll
    for (int i = 0; i < 4; i++)
#pragma unroll
        for (int j = 0; j < 4; j++)
#pragma unroll
            for (int c = 0; c < 4; c++) acc[i][j][c] = 0.0f;

    const int nstage = K >> 5;
    if (ldme) {
#pragma unroll
        for (int h = 0; h < 2; ++h) {
            int row = rr + h * 64;
            const uint16_t* src = gsrc + (size_t)row * K;
            uint32_t d = sdst + row * (GASTRIDE * 2);
#pragma unroll
            for (int c = 0; c < 4; ++c) cp16(d + c * 16, src + c * 8);
        }
    }
    CP_COMMIT();

    for (int s = 0; s < nstage; ++s) {
        if (s + 1 < nstage) {
            const int k0 = (s + 1) << 5;
            const uint32_t boff = ((s + 1) & 1) * GSTAGE;
            if (ldme) {
#pragma unroll
                for (int h = 0; h < 2; ++h) {
                    int row = rr + h * 64;
                    const uint16_t* src = gsrc + (size_t)row * K + k0;
                    uint32_t d = sdst + boff + row * (GASTRIDE * 2);
#pragma unroll
                    for (int c = 0; c < 4; ++c) cp16(d + c * 16, src + c * 8);
                }
            }
            CP_COMMIT();
            CP_WAIT1();
        } else {
            CP_WAIT0();
        }
        __syncthreads();

        const uint32_t sb = smem_base + (s & 1) * GSTAGE;
        const uint32_t sbB = sb + 2 * GMAT_BYTES;
#pragma unroll
        for (int kc = 0; kc < 32; kc += 16) {
            uint32_t ah[4][4], bh[4][2];
#pragma unroll
            for (int i = 0; i < 4; ++i)
                ldsm_x4(ah[i], sb + (wm + 16 * i + aRowOff) * (GASTRIDE * 2)
                                  + (kc + aColOff) * 2);
#pragma unroll
            for (int j = 0; j < 4; ++j)
                ldsm_x2(bh[j], sbB + (wn + 8 * j + bRowOff) * (GASTRIDE * 2)
                                   + (kc + bColOff) * 2);
            if (fp1) {
#pragma unroll
                for (int i = 0; i < 4; ++i)
#pragma unroll
                    for (int j = 0; j < 4; ++j)
                        mma16816h(acc[i][j], ah[i], bh[j]);
            } else {
#pragma unroll
                for (int i = 0; i < 4; ++i)
#pragma unroll
                    for (int j = 0; j < 4; ++j)
                        mma16816(acc[i][j], ah[i], bh[j]);
            }
        }
        __syncthreads();
    }

    // ---- epilogue ----
    const int er = lane >> 2;
    const int ec = (lane & 3) * 2;
#pragma unroll
    for (int j = 0; j < 4; ++j) {
        const int n = n0 + wn + 8 * j + ec;
        const float b0 = bias[n], b1 = bias[n + 1];
#pragma unroll
        for (int i = 0; i < 4; ++i) {
            const int m = m0 + wm + 16 * i + er;
            float v0 = acc[i][j][0] + b0, v1 = acc[i][j][1] + b1;
            float v2 = acc[i][j][2] + b0, v3 = acc[i][j][3] + b1;
            if (OM == 1) {
                *(float2*)(Cf + (size_t)m * N + n)       = make_float2(v0, v1);
                *(float2*)(Cf + (size_t)(m + 8) * N + n) = make_float2(v2, v3);
            } else if (!isV) {
                *(__nv_bfloat162*)(Cb + (size_t)m * NQK + n) =
                    __halves2bfloat162(__float2bfloat16(v0), __float2bfloat16(v1));
                *(__nv_bfloat162*)(Cb + (size_t)(m + 8) * NQK + n) =
                    __halves2bfloat162(__float2bfloat16(v2), __float2bfloat16(v3));
            } else {
                const int nv = n - NQK;
                *(__half2*)(Cv + (size_t)m * NQKV + nv)       = __floats2half2_rn(v0, v1);
                *(__half2*)(Cv + (size_t)(m + 8) * NQKV + nv) = __floats2half2_rn(v2, v3);
            }
        }
    }
}

// -------------------- HMMA flash attention: bf16 S, fp16 PV, fp16 AO -----------
#define ASTR 72   // 16-bit elems per smem row

__global__ __launch_bounds__(128)
void attn_mma(const __nv_bfloat16* __restrict__ QKb, const __half* __restrict__ Vf,
              __half* __restrict__ AOf) {
    __shared__ __align__(16) __nv_bfloat16 Qs[64 * ASTR];
    __shared__ __align__(16) __nv_bfloat16 Ks[64 * ASTR];
    __shared__ __align__(16) __half        Vs[64 * ASTR];

    const int tid = threadIdx.x, wid = tid >> 5, lane = tid & 31;
    const int q0 = blockIdx.x * 64, h = blockIdx.y, b = blockIdx.z;
    const size_t rowbase = (size_t)b * SEQ;
    const int coff = h * DHEAD;

    const __nv_bfloat16* Qp = QKb + coff;          // stride NQK
    const __nv_bfloat16* Kp = QKb + 512 + coff;    // stride NQK
    const __half*        Vp = Vf + coff;           // stride NQKV

    const int lr = tid >> 1, lc = (tid & 1) * 32;
    {
        const __nv_bfloat16* src = Qp + (rowbase + q0 + lr) * NQK + lc;
#pragma unroll
        for (int c = 0; c < 4; ++c)
            *(uint4*)&Qs[lr * ASTR + lc + 8 * c] = *(const uint4*)(src + 8 * c);
    }
    __syncthreads();

    const uint32_t qbase = smem_to_u32(Qs), kbase = smem_to_u32(Ks);
    const uint32_t vbase = smem_to_u32(Vs);
    const int wq = wid * 16;

    uint32_t qf[4][4];
#pragma unroll
    for (int ks = 0; ks < 4; ++ks)
        ldsm_x4(qf[ks], qbase + ((wq + (lane & 15)) * ASTR + ks * 16
                                 + ((lane & 16) ? 8 : 0)) * 2);

    float oacc[8][4];
#pragma unroll
    for (int j = 0; j < 8; ++j)
#pragma unroll
        for (int c = 0; c < 4; ++c) oacc[j][c] = 0.0f;
    float mrow0 = -1e30f, mrow1 = -1e30f, lrow0 = 0.0f, lrow1 = 0.0f;

    for (int kv0 = 0; kv0 < SEQ; kv0 += 64) {
        __syncthreads();
        {
            const size_t krow = (rowbase + kv0 + lr) * NQK + lc;
            const size_t vrow = (rowbase + kv0 + lr) * NQKV + lc;
            const int so = lr * ASTR + lc;
#pragma unroll
            for (int c = 0; c < 4; ++c) {
                *(uint4*)&Ks[so + 8 * c] = *(const uint4*)(Kp + krow + 8 * c);
                *(uint4*)&Vs[so + 8 * c] = *(const uint4*)(Vp + vrow + 8 * c);
            }
        }
        __syncthreads();

        // ---- S = Q @ K^T (bf16) ----
        float s[8][4];
#pragma unroll
        for (int j = 0; j < 8; ++j)
#pragma unroll
            for (int c = 0; c < 4; ++c) s[j][c] = 0.0f;
#pragma unroll
        for (int ks = 0; ks < 4; ++ks)
#pragma unroll
            for (int j = 0; j < 8; ++j) {
                uint32_t kf[2];
                ldsm_x2(kf, kbase + ((8 * j + (lane & 7)) * ASTR + ks * 16
                                     + ((lane & 8) ? 8 : 0)) * 2);
                mma16816(s[j], qf[ks], kf);
            }

        // ---- register softmax ----
        float tmax0 = -1e30f, tmax1 = -1e30f;
#pragma unroll
        for (int j = 0; j < 8; ++j) {
            s[j][0] *= 0.125f; s[j][1] *= 0.125f; s[j][2] *= 0.125f; s[j][3] *= 0.125f;
            tmax0 = fmaxf(tmax0, fmaxf(s[j][0], s[j][1]));
            tmax1 = fmaxf(tmax1, fmaxf(s[j][2], s[j][3]));
        }
        tmax0 = fmaxf(tmax0, __shfl_xor_sync(0xffffffffu, tmax0, 1));
        tmax0 = fmaxf(tmax0, __shfl_xor_sync(0xffffffffu, tmax0, 2));
        tmax1 = fmaxf(tmax1, __shfl_xor_sync(0xffffffffu, tmax1, 1));
        tmax1 = fmaxf(tmax1, __shfl_xor_sync(0xffffffffu, tmax1, 2));

        float nm0 = fmaxf(mrow0, tmax0), nm1 = fmaxf(mrow1, tmax1);
        float corr0 = __expf(mrow0 - nm0), corr1 = __expf(mrow1 - nm1);
        mrow0 = nm0; mrow1 = nm1;
#pragma unroll
        for (int j = 0; j < 8; ++j) {
            oacc[j][0] *= corr0; oacc[j][1] *= corr0;
            oacc[j][2] *= corr1; oacc[j][3] *= corr1;
        }

        float ps0 = 0.0f, ps1 = 0.0f;
        uint32_t aH[4][4];     // P fragments in fp16
#pragma unroll
        for (int j = 0; j < 8; ++j) {
            float p0 = __expf(s[j][0] - nm0), p1 = __expf(s[j][1] - nm0);
            float p2 = __expf(s[j][2] - nm1), p3 = __expf(s[j][3] - nm1);
            ps0 += p0 + p1; ps1 += p2 + p3;
            const int jp = j >> 1, sel = (j & 1) * 2;
            aH[jp][sel + 0] = pkhf2(p0, p1);
            aH[jp][sel + 1] = pkhf2(p2, p3);
        }
        ps0 += __shfl_xor_sync(0xffffffffu, ps0, 1);
        ps0 += __shfl_xor_sync(0xffffffffu, ps0, 2);
        ps1 += __shfl_xor_sync(0xffffffffu, ps1, 1);
        ps1 += __shfl_xor_sync(0xffffffffu, ps1, 2);
        lrow0 = lrow0 * corr0 + ps0;
        lrow1 = lrow1 * corr1 + ps1;

        // ---- O += P @ V (fp16, single product) ----
#pragma unroll
        for (int jd = 0; jd < 8; ++jd)
#pragma unroll
            for (int ks = 0; ks < 4; ++ks) {
                uint32_t v2[2];
                ldsm_x2t(v2, vbase + ((16 * ks + (lane & 15)) * ASTR + 8 * jd) * 2);
                mma16816h(oacc[jd], aH[ks], v2);
            }
    }

    const float inv0 = 1.0f / lrow0, inv1 = 1.0f / lrow1;
    const int er = lane >> 2, ec = (lane & 3) * 2;
    const size_t r0o = (rowbase + q0 + wq + er) * NQKV + coff;
    const size_t r1o = r0o + (size_t)8 * NQKV;
#pragma unroll
    for (int jd = 0; jd < 8; ++jd) {
        const int n = 8 * jd + ec;
        *(__half2*)&AOf[r0o + n] = __floats2half2_rn(oacc[jd][0] * inv0,
                                                     oacc[jd][1] * inv0);
        *(__half2*)&AOf[r1o + n] = __floats2half2_rn(oacc[jd][2] * inv1,
                                                     oacc[jd][3] * inv1);
    }
}

// -------------------- launch ---------------------------------------------------
extern "C" void kernel_launch(void* const* d_in, const int* in_sizes, int n_in,
                              void* d_out, int out_size) {
    const float* x  = (const float*)d_in[0];
    const float* Wq = (const float*)d_in[1];
    const float* bq = (const float*)d_in[2];
    const float* Wk = (const float*)d_in[3];
    const float* bk = (const float*)d_in[4];
    const float* Wv = (const float*)d_in[5];
    const float* bv = (const float*)d_in[6];
    const float* Wo = (const float*)d_in[7];
    const float* bo = (const float*)d_in[8];
    float* out = (float*)d_out;

    __nv_bfloat16 *xh, *xl, *qkb, *wqkh, *wqkl;
    __half *xf, *vf, *aof, *wvf, *wof;
    float* bcat;
    cudaGetSymbolAddress((void**)&xh,   g_xh);   cudaGetSymbolAddress((void**)&xl,   g_xl);
    cudaGetSymbolAddress((void**)&xf,   g_xf);
    cudaGetSymbolAddress((void**)&qkb,  g_qkb);  cudaGetSymbolAddress((void**)&vf,   g_vf);
    cudaGetSymbolAddress((void**)&aof,  g_aof);
    cudaGetSymbolAddress((void**)&wqkh, g_wqkh); cudaGetSymbolAddress((void**)&wqkl, g_wqkl);
    cudaGetSymbolAddress((void**)&wvf,  g_wvf);  cudaGetSymbolAddress((void**)&wof,  g_wof);
    cudaGetSymbolAddress((void**)&bcat, g_bcat);

    cudaFuncSetAttribute(gemm_mp<1>, cudaFuncAttributeMaxDynamicSharedMemorySize, GSM_TOTAL);
    cudaFuncSetAttribute(gemm_mp<3>, cudaFuncAttributeMaxDynamicSharedMemorySize, GSM_TOTAL);

    // 1) split x -> bf16 hi/lo + fp16; bias concat
    split3_kernel<<<(NTOK * DMODEL / 2 + 255) / 256, 256>>>(x, xh, xl, xf, NTOK * DMODEL / 2);
    bias_cat<<<(NCAT + 255) / 256, 256>>>(bq, bk, bv, bcat);

    // 2) transpose weights: Wq,Wk -> bf16 h/l; Wv -> fp16; Wo -> fp16
    dim3 tb(32, 8);
    transpose_split3<<<dim3(NQKV / 32, DMODEL / 32, 3), tb>>>(
        Wq, wqkh, wqkl,
        Wk, wqkh + (size_t)512 * DMODEL, wqkl + (size_t)512 * DMODEL,
        Wv, (__nv_bfloat16*)wvf, nullptr,
        DMODEL, NQKV, /*fpz=*/2);
    transpose_split3<<<dim3(DMODEL / 32, NQKV / 32, 1), tb>>>(
        Wo, (__nv_bfloat16*)wof, nullptr, nullptr, nullptr, nullptr,
        nullptr, nullptr, nullptr, NQKV, DMODEL, /*fpz=*/0);

    // 3) fused QKV projection: Q,K 1-prod bf16 -> qkb; V 1-prod fp16 -> vf
    dim3 gq(NCAT / 128, NTOK / 128);
    gemm_mp<3><<<gq, 256, GSM_TOTAL>>>(
        (const uint16_t*)xh, (const uint16_t*)xl, (const uint16_t*)xf,
        (const uint16_t*)wqkh, (const uint16_t*)wqkl, (const uint16_t*)wvf,
        bcat, nullptr, qkb, vf, DMODEL, NCAT);

    // 4) flash attention: bf16 S + fp16 PV -> AO fp16
    dim3 ga(SEQ / 64, NHEAD, 8);
    attn_mma<<<ga, 128>>>(qkb, vf, aof);

    // 5) output projection (1-product fp16, fp32 out): [8192,512] @ [1024,512]^T
    dim3 go(DMODEL / 128, NTOK / 128);
    gemm_mp<1><<<go, 256, GSM_TOTAL>>>(
        (const uint16_t*)aof, nullptr, nullptr,
        (const uint16_t*)wof, nullptr, nullptr,
        bo, out, nullptr, nullptr, NQKV, DMODEL);
}